// round 6
// baseline (speedup 1.0000x reference)
#include <cuda_runtime.h>
#include <math.h>

#define NMAX 50000
#define EMAX 500000
#define GMAX 64
#define FDIM 128
#define CDIM 5
#define NEG  0.2f

// ---------------- scratch (device globals; no allocation) ----------------
__device__ int   g_is64;
__device__ int   g_src[EMAX];
__device__ int   g_dst[EMAX];
__device__ int   g_batch[NMAX];
__device__ int   g_deg[NMAX];
__device__ int   g_cnt[NMAX];
__device__ int   g_rowptr[NMAX + 1];
__device__ int   g_srcs[EMAX];
__device__ int   g_bsum[128];
__device__ int   g_boff[128];
__device__ float g_bufA[(size_t)NMAX * FDIM];   // post-aggregation features (layer input)
__device__ float g_bufB[(size_t)NMAX * FDIM];   // post-GEMM h
__device__ float g_asrc[NMAX * 2];
__device__ float g_adst[NMAX * 2];
__device__ float g_gsum[GMAX * FDIM];
__device__ int   g_gcnt[GMAX];

__device__ __forceinline__ float lrelu(float x) { return x > 0.f ? x : NEG * x; }

// ---------------- preprocessing ----------------

// Detect int64 vs int32 edge_index: if values are int64 (< 2^31), every odd
// 32-bit word is 0. Random src indices in [0,50000) make a false positive
// over up-to-128 samples vanishingly unlikely. Also zero pooling accumulators.
__global__ void k_detect(const int* __restrict__ ew, int E) {
    __shared__ int nz;
    if (threadIdx.x == 0) nz = 0;
    __syncthreads();
    int nsamp = E < 128 ? E : 128;
    if (threadIdx.x < nsamp && ew[2 * threadIdx.x + 1] != 0) atomicAdd(&nz, 1);
    for (int i = threadIdx.x; i < GMAX * FDIM; i += blockDim.x) g_gsum[i] = 0.f;
    for (int i = threadIdx.x; i < GMAX;        i += blockDim.x) g_gcnt[i] = 0;
    __syncthreads();
    if (threadIdx.x == 0) g_is64 = (nz == 0) ? 1 : 0;
}

__global__ void k_init(const void* __restrict__ bt, int N) {
    int n = blockIdx.x * blockDim.x + threadIdx.x;
    if (n >= N) return;
    g_deg[n] = 0;
    int b = g_is64 ? (int)((const long long*)bt)[n] : ((const int*)bt)[n];
    g_batch[n] = b;
    atomicAdd(&g_gcnt[b], 1);
}

__global__ void k_convert(const void* __restrict__ ei, int E) {
    int e = blockIdx.x * blockDim.x + threadIdx.x;
    if (e >= E) return;
    if (g_is64) {
        const long long* p = (const long long*)ei;
        g_src[e] = (int)p[e];
        g_dst[e] = (int)p[(size_t)E + e];
    } else {
        const int* p = (const int*)ei;
        g_src[e] = p[e];
        g_dst[e] = p[E + e];
    }
}

__global__ void k_degree(int E) {
    int e = blockIdx.x * blockDim.x + threadIdx.x;
    if (e < E) atomicAdd(&g_deg[g_dst[e]], 1);
}

#define SCB 1024
__global__ void k_scan1(int N) {
    __shared__ int sh[SCB];
    int i = blockIdx.x * SCB + threadIdx.x;
    int v = (i < N) ? g_deg[i] : 0;
    sh[threadIdx.x] = v;
    __syncthreads();
    for (int off = 1; off < SCB; off <<= 1) {
        int t = (threadIdx.x >= off) ? sh[threadIdx.x - off] : 0;
        __syncthreads();
        sh[threadIdx.x] += t;
        __syncthreads();
    }
    if (i < N) g_rowptr[i] = sh[threadIdx.x] - v;           // exclusive
    if (threadIdx.x == SCB - 1) g_bsum[blockIdx.x] = sh[SCB - 1];
}

__global__ void k_scan2(int nb) {
    __shared__ int sh[128];
    int v = (threadIdx.x < nb) ? g_bsum[threadIdx.x] : 0;
    sh[threadIdx.x] = v;
    __syncthreads();
    for (int off = 1; off < 128; off <<= 1) {
        int t = (threadIdx.x >= off) ? sh[threadIdx.x - off] : 0;
        __syncthreads();
        sh[threadIdx.x] += t;
        __syncthreads();
    }
    g_boff[threadIdx.x] = sh[threadIdx.x] - v;               // exclusive
}

__global__ void k_scan3(int N, int E) {
    int i = blockIdx.x * blockDim.x + threadIdx.x;
    if (i < N) {
        g_rowptr[i] += g_boff[i / SCB];
        g_cnt[i] = 0;
    }
    if (i == 0) g_rowptr[N] = E;
}

__global__ void k_scatter(int E) {
    int e = blockIdx.x * blockDim.x + threadIdx.x;
    if (e >= E) return;
    int d = g_dst[e];
    int pos = g_rowptr[d] + atomicAdd(&g_cnt[d], 1);
    g_srcs[pos] = g_src[e];
}

// ---------------- layer 1 GEMM (K=4), fused alpha ----------------
__global__ __launch_bounds__(256) void k_gemm1(const float* __restrict__ x,
                                               const float* __restrict__ W,
                                               const float* __restrict__ asrc,
                                               const float* __restrict__ adst, int N) {
    __shared__ float Wsh[4 * 128];
    __shared__ float s_as[128], s_ad[128];
    int t = threadIdx.x;
    for (int i = t; i < 512; i += 256) Wsh[i] = W[i];
    if (t < 128) { s_as[t] = asrc[t]; s_ad[t] = adst[t]; }
    __syncthreads();
    int warp = t >> 5, lane = t & 31;
    int n = blockIdx.x * 8 + warp;
    if (n >= N) return;
    float4 xv = *(const float4*)(x + (size_t)n * 4);
    int j0 = lane * 4;
    float o[4];
    float ps = 0.f, pd = 0.f;
#pragma unroll
    for (int j = 0; j < 4; j++) {
        int c = j0 + j;
        float val = xv.x * Wsh[c] + xv.y * Wsh[128 + c] + xv.z * Wsh[256 + c] + xv.w * Wsh[384 + c];
        o[j] = val;
        ps = fmaf(val, s_as[c], ps);
        pd = fmaf(val, s_ad[c], pd);
    }
    *(float4*)(g_bufB + (size_t)n * FDIM + j0) = make_float4(o[0], o[1], o[2], o[3]);
#pragma unroll
    for (int off = 8; off >= 1; off >>= 1) {
        ps += __shfl_xor_sync(0xffffffffu, ps, off);
        pd += __shfl_xor_sync(0xffffffffu, pd, off);
    }
    if (lane == 0)  { g_asrc[n * 2]     = ps; g_adst[n * 2]     = pd; }
    if (lane == 16) { g_asrc[n * 2 + 1] = ps; g_adst[n * 2 + 1] = pd; }
}

// ---------------- big GEMM (M=N, K=128, Ncol=128), fused alpha ----------------
// Block: 64 rows x 128 cols, 128 threads, 8x8 microtile, BK=32 chunks.
__global__ __launch_bounds__(128) void k_gemm(const float* __restrict__ W,
                                              const float* __restrict__ asrc,
                                              const float* __restrict__ adst, int N) {
    __shared__ float Wsh[32 * 128];
    __shared__ float Ash[64 * 33];
    __shared__ float s_as[128], s_ad[128];
    int t = threadIdx.x;
    int tc = t & 15, tr = t >> 4;
    int c0 = tc * 8, r0 = tr * 8;
    int rowBase = blockIdx.x * 64;
    s_as[t] = asrc[t];
    s_ad[t] = adst[t];
    float acc[8][8];
#pragma unroll
    for (int i = 0; i < 8; i++)
#pragma unroll
        for (int j = 0; j < 8; j++) acc[i][j] = 0.f;

    for (int k0 = 0; k0 < 128; k0 += 32) {
        __syncthreads();
#pragma unroll
        for (int i = 0; i < 8; i++) {
            int idx = t + i * 128;      // 1024 float4 = 32x128 floats
            ((float4*)Wsh)[idx] = ((const float4*)(W + k0 * 128))[idx];
        }
#pragma unroll
        for (int i = 0; i < 4; i++) {
            int li = t + i * 128;       // 512 float4 = 64x32 floats
            int r  = li >> 3;
            int cc = (li & 7) * 4;
            float4 v = make_float4(0.f, 0.f, 0.f, 0.f);
            int row = rowBase + r;
            if (row < N) v = *(const float4*)(g_bufA + (size_t)row * FDIM + k0 + cc);
            Ash[r * 33 + cc + 0] = v.x; Ash[r * 33 + cc + 1] = v.y;
            Ash[r * 33 + cc + 2] = v.z; Ash[r * 33 + cc + 3] = v.w;
        }
        __syncthreads();
#pragma unroll
        for (int kk = 0; kk < 32; kk++) {
            float a[8];
#pragma unroll
            for (int i = 0; i < 8; i++) a[i] = Ash[(r0 + i) * 33 + kk];
            float4 b0 = *(const float4*)&Wsh[kk * 128 + c0];
            float4 b1 = *(const float4*)&Wsh[kk * 128 + c0 + 4];
            float bb[8] = { b0.x, b0.y, b0.z, b0.w, b1.x, b1.y, b1.z, b1.w };
#pragma unroll
            for (int i = 0; i < 8; i++)
#pragma unroll
                for (int j = 0; j < 8; j++) acc[i][j] = fmaf(a[i], bb[j], acc[i][j]);
        }
    }

    // fused alpha_src / alpha_dst: c0 spans 8 cols of one head (tc<8 -> head0)
    float ps[8], pd[8];
#pragma unroll
    for (int i = 0; i < 8; i++) {
        float s = 0.f, d = 0.f;
#pragma unroll
        for (int j = 0; j < 8; j++) {
            s = fmaf(acc[i][j], s_as[c0 + j], s);
            d = fmaf(acc[i][j], s_ad[c0 + j], d);
        }
        ps[i] = s; pd[i] = d;
    }
#pragma unroll
    for (int off = 4; off >= 1; off >>= 1) {
#pragma unroll
        for (int i = 0; i < 8; i++) {
            ps[i] += __shfl_xor_sync(0xffffffffu, ps[i], off);
            pd[i] += __shfl_xor_sync(0xffffffffu, pd[i], off);
        }
    }
#pragma unroll
    for (int i = 0; i < 8; i++) {
        int row = rowBase + r0 + i;
        if (row < N) {
            *(float4*)(g_bufB + (size_t)row * FDIM + c0)     = make_float4(acc[i][0], acc[i][1], acc[i][2], acc[i][3]);
            *(float4*)(g_bufB + (size_t)row * FDIM + c0 + 4) = make_float4(acc[i][4], acc[i][5], acc[i][6], acc[i][7]);
            if (tc == 0) { g_asrc[row * 2]     = ps[i]; g_adst[row * 2]     = pd[i]; }
            if (tc == 8) { g_asrc[row * 2 + 1] = ps[i]; g_adst[row * 2 + 1] = pd[i]; }
        }
    }
}

// ---------------- aggregation: warp per dst node (CSR), no float atomics ----------------
__global__ __launch_bounds__(256) void k_agg(const float* __restrict__ bias, int N) {
    int warp = threadIdx.x >> 5, lane = threadIdx.x & 31;
    int v = blockIdx.x * 8 + warp;
    if (v >= N) return;
    int f0 = lane * 4;
    int head = lane >> 4;
    float4 bv = *(const float4*)(bias + f0);
    int start = g_rowptr[v], end = g_rowptr[v + 1];
    if (start == end) {
        float4 outv = make_float4(fmaxf(bv.x, 0.f), fmaxf(bv.y, 0.f),
                                  fmaxf(bv.z, 0.f), fmaxf(bv.w, 0.f));
        *(float4*)(g_bufA + (size_t)v * FDIM + f0) = outv;
        return;
    }
    float ad0 = g_adst[v * 2], ad1 = g_adst[v * 2 + 1];
    // pass 1: segment max per head
    float m0 = -3e38f, m1 = -3e38f;
    for (int e = start + lane; e < end; e += 32) {
        int s = g_srcs[e];
        float2 as = *(const float2*)(g_asrc + s * 2);
        m0 = fmaxf(m0, lrelu(as.x + ad0));
        m1 = fmaxf(m1, lrelu(as.y + ad1));
    }
#pragma unroll
    for (int off = 16; off >= 1; off >>= 1) {
        m0 = fmaxf(m0, __shfl_xor_sync(0xffffffffu, m0, off));
        m1 = fmaxf(m1, __shfl_xor_sync(0xffffffffu, m1, off));
    }
    // pass 2: exp once per edge (lane-parallel), broadcast BOTH heads' weights
    // via shfl and select with the RECEIVER's head, then gather h[src].
    float d0 = 0.f, d1 = 0.f;
    float4 acc = make_float4(0.f, 0.f, 0.f, 0.f);
    for (int base = start; base < end; base += 32) {
        int e = base + lane;
        float w0 = 0.f, w1 = 0.f;
        int s = 0;
        if (e < end) {
            s = g_srcs[e];
            float2 as = *(const float2*)(g_asrc + s * 2);
            w0 = __expf(lrelu(as.x + ad0) - m0);
            w1 = __expf(lrelu(as.y + ad1) - m1);
            d0 += w0; d1 += w1;
        }
        int cnt = min(32, end - base);
        for (int i = 0; i < cnt; i++) {
            float ww0 = __shfl_sync(0xffffffffu, w0, i);
            float ww1 = __shfl_sync(0xffffffffu, w1, i);
            int   si  = __shfl_sync(0xffffffffu, s, i);
            float w   = head ? ww1 : ww0;
            float4 hv = *(const float4*)(g_bufB + (size_t)si * FDIM + f0);
            acc.x = fmaf(w, hv.x, acc.x);
            acc.y = fmaf(w, hv.y, acc.y);
            acc.z = fmaf(w, hv.z, acc.z);
            acc.w = fmaf(w, hv.w, acc.w);
        }
    }
#pragma unroll
    for (int off = 16; off >= 1; off >>= 1) {
        d0 += __shfl_xor_sync(0xffffffffu, d0, off);
        d1 += __shfl_xor_sync(0xffffffffu, d1, off);
    }
    float inv = 1.f / ((head ? d1 : d0) + 1e-16f);
    float4 outv;
    outv.x = fmaxf(fmaf(acc.x, inv, bv.x), 0.f);
    outv.y = fmaxf(fmaf(acc.y, inv, bv.y), 0.f);
    outv.z = fmaxf(fmaf(acc.z, inv, bv.z), 0.f);
    outv.w = fmaxf(fmaf(acc.w, inv, bv.w), 0.f);
    *(float4*)(g_bufA + (size_t)v * FDIM + f0) = outv;
}

// ---------------- pooling: chunked accumulation (sorted batch -> few atomics) ----------------
__global__ void k_pool(int N) {
    int fg = blockIdx.y;                                   // 0..31 (float4 group)
    int chunk = blockIdx.x * blockDim.x + threadIdx.x;
    int n0 = chunk * 16;
    if (n0 >= N) return;
    int f0 = fg * 4;
    int nend = min(n0 + 16, N);
    float4 acc = make_float4(0.f, 0.f, 0.f, 0.f);
    int cur = g_batch[n0];
    for (int n = n0; n < nend; n++) {
        int b = g_batch[n];
        if (b != cur) {
            atomicAdd(&g_gsum[cur * FDIM + f0 + 0], acc.x);
            atomicAdd(&g_gsum[cur * FDIM + f0 + 1], acc.y);
            atomicAdd(&g_gsum[cur * FDIM + f0 + 2], acc.z);
            atomicAdd(&g_gsum[cur * FDIM + f0 + 3], acc.w);
            acc = make_float4(0.f, 0.f, 0.f, 0.f);
            cur = b;
        }
        float4 v = *(const float4*)(g_bufA + (size_t)n * FDIM + f0);
        acc.x += v.x; acc.y += v.y; acc.z += v.z; acc.w += v.w;
    }
    atomicAdd(&g_gsum[cur * FDIM + f0 + 0], acc.x);
    atomicAdd(&g_gsum[cur * FDIM + f0 + 1], acc.y);
    atomicAdd(&g_gsum[cur * FDIM + f0 + 2], acc.z);
    atomicAdd(&g_gsum[cur * FDIM + f0 + 3], acc.w);
}

// ---------------- head: mean, linear [128->5], sigmoid ----------------
__global__ void k_head(const float* __restrict__ lw, const float* __restrict__ lb,
                       float* __restrict__ out) {
    int g = blockIdx.x, t = threadIdx.x;
    __shared__ float red[CDIM][128];
    float cnt = fmaxf((float)g_gcnt[g], 1.0f);
    float p = g_gsum[g * FDIM + t] / cnt;
#pragma unroll
    for (int c = 0; c < CDIM; c++) red[c][t] = p * lw[t * CDIM + c];
    __syncthreads();
    for (int s = 64; s >= 1; s >>= 1) {
        if (t < s) {
#pragma unroll
            for (int c = 0; c < CDIM; c++) red[c][t] += red[c][t + s];
        }
        __syncthreads();
    }
    if (t < CDIM) out[g * CDIM + t] = 1.f / (1.f + __expf(-(red[t][0] + lb[t])));
}

// ---------------- launch ----------------
extern "C" void kernel_launch(void* const* d_in, const int* in_sizes, int n_in,
                              void* d_out, int out_size) {
    const float* x   = (const float*)d_in[0];
    const void*  ei  = d_in[1];
    const void*  bt  = d_in[2];
    const float* W1  = (const float*)d_in[3];
    const float* as1 = (const float*)d_in[4];
    const float* ad1 = (const float*)d_in[5];
    const float* b1  = (const float*)d_in[6];
    const float* Wl[3]  = { (const float*)d_in[7],  (const float*)d_in[11], (const float*)d_in[15] };
    const float* asl[3] = { (const float*)d_in[8],  (const float*)d_in[12], (const float*)d_in[16] };
    const float* adl[3] = { (const float*)d_in[9],  (const float*)d_in[13], (const float*)d_in[17] };
    const float* bl[3]  = { (const float*)d_in[10], (const float*)d_in[14], (const float*)d_in[18] };
    const float* lw = (const float*)d_in[19];
    const float* lb = (const float*)d_in[20];

    int N = in_sizes[0] / 4;        // F_IN = 4
    int E = in_sizes[1] / 2;        // element count = 2*E for both int32/int64
    int G = out_size / CDIM;

    // preprocessing: dtype detect, convert, CSR by dst
    k_detect<<<1, 128>>>((const int*)ei, E);
    k_init<<<(N + 255) / 256, 256>>>(bt, N);
    k_convert<<<(E + 255) / 256, 256>>>(ei, E);
    k_degree<<<(E + 255) / 256, 256>>>(E);
    int nb = (N + SCB - 1) / SCB;
    k_scan1<<<nb, SCB>>>(N);
    k_scan2<<<1, 128>>>(nb);
    k_scan3<<<(N + 255) / 256, 256>>>(N, E);
    k_scatter<<<(E + 255) / 256, 256>>>(E);

    // layer 1
    k_gemm1<<<(N + 7) / 8, 256>>>(x, W1, as1, ad1, N);
    k_agg<<<(N + 7) / 8, 256>>>(b1, N);
    // layers 2..4
    for (int l = 0; l < 3; l++) {
        k_gemm<<<(N + 63) / 64, 128>>>(Wl[l], asl[l], adl[l], N);
        k_agg<<<(N + 7) / 8, 256>>>(bl[l], N);
    }

    // pool + head
    int chunks = (N + 15) / 16;
    dim3 pg((chunks + 63) / 64, 32);
    k_pool<<<pg, 64>>>(N);
    k_head<<<G, 128>>>(lw, lb, (float*)d_out);
}

// round 12
// speedup vs baseline: 1.2278x; 1.2278x over previous
#include <cuda_runtime.h>
#include <cuda_bf16.h>
#include <math.h>
#include <stdint.h>

#define NMAX 50000
#define EMAX 500000
#define GMAX 64
#define FDIM 128
#define CDIM 5
#define NEG  0.2f

// ---------------- scratch (device globals; no allocation) ----------------
__device__ int   g_is64;
__device__ int   g_src[EMAX];
__device__ int   g_dst[EMAX];
__device__ int   g_batch[NMAX];
__device__ int   g_deg[NMAX];
__device__ int   g_cnt[NMAX];
__device__ int   g_rowptr[NMAX + 1];
__device__ int   g_srcs[EMAX];
__device__ int   g_bsum[128];
__device__ int   g_boff[128];
__device__ float g_bufA[(size_t)NMAX * FDIM];   // post-aggregation features (layer input)
__device__ float g_bufB[(size_t)NMAX * FDIM];   // post-GEMM h
__device__ float g_asrc[NMAX * 2];
__device__ float g_adst[NMAX * 2];
__device__ float g_gsum[GMAX * FDIM];
__device__ int   g_gcnt[GMAX];

__device__ __forceinline__ float lrelu(float x) { return x > 0.f ? x : NEG * x; }

// ---------------- preprocessing ----------------
__global__ void k_detect(const int* __restrict__ ew, int E) {
    __shared__ int nz;
    if (threadIdx.x == 0) nz = 0;
    __syncthreads();
    int nsamp = E < 128 ? E : 128;
    if (threadIdx.x < nsamp && ew[2 * threadIdx.x + 1] != 0) atomicAdd(&nz, 1);
    for (int i = threadIdx.x; i < GMAX * FDIM; i += blockDim.x) g_gsum[i] = 0.f;
    for (int i = threadIdx.x; i < GMAX;        i += blockDim.x) g_gcnt[i] = 0;
    __syncthreads();
    if (threadIdx.x == 0) g_is64 = (nz == 0) ? 1 : 0;
}

__global__ void k_init(const void* __restrict__ bt, int N) {
    int n = blockIdx.x * blockDim.x + threadIdx.x;
    if (n >= N) return;
    g_deg[n] = 0;
    int b = g_is64 ? (int)((const long long*)bt)[n] : ((const int*)bt)[n];
    g_batch[n] = b;
    atomicAdd(&g_gcnt[b], 1);
}

// fused convert + degree (one pass over the edge list)
__global__ void k_convert_degree(const void* __restrict__ ei, int E) {
    int e = blockIdx.x * blockDim.x + threadIdx.x;
    if (e >= E) return;
    int s, d;
    if (g_is64) {
        const long long* p = (const long long*)ei;
        s = (int)p[e]; d = (int)p[(size_t)E + e];
    } else {
        const int* p = (const int*)ei;
        s = p[e]; d = p[E + e];
    }
    g_src[e] = s; g_dst[e] = d;
    atomicAdd(&g_deg[d], 1);
}

#define SCB 1024
__global__ void k_scan1(int N) {
    __shared__ int sh[SCB];
    int i = blockIdx.x * SCB + threadIdx.x;
    int v = (i < N) ? g_deg[i] : 0;
    sh[threadIdx.x] = v;
    __syncthreads();
    for (int off = 1; off < SCB; off <<= 1) {
        int t = (threadIdx.x >= off) ? sh[threadIdx.x - off] : 0;
        __syncthreads();
        sh[threadIdx.x] += t;
        __syncthreads();
    }
    if (i < N) g_rowptr[i] = sh[threadIdx.x] - v;
    if (threadIdx.x == SCB - 1) g_bsum[blockIdx.x] = sh[SCB - 1];
}

__global__ void k_scan2(int nb) {
    __shared__ int sh[128];
    int v = (threadIdx.x < nb) ? g_bsum[threadIdx.x] : 0;
    sh[threadIdx.x] = v;
    __syncthreads();
    for (int off = 1; off < 128; off <<= 1) {
        int t = (threadIdx.x >= off) ? sh[threadIdx.x - off] : 0;
        __syncthreads();
        sh[threadIdx.x] += t;
        __syncthreads();
    }
    g_boff[threadIdx.x] = sh[threadIdx.x] - v;
}

__global__ void k_scan3(int N, int E) {
    int i = blockIdx.x * blockDim.x + threadIdx.x;
    if (i < N) {
        g_rowptr[i] += g_boff[i / SCB];
        g_cnt[i] = 0;
    }
    if (i == 0) g_rowptr[N] = E;
}

__global__ void k_scatter(int E) {
    int e = blockIdx.x * blockDim.x + threadIdx.x;
    if (e >= E) return;
    int d = g_dst[e];
    int pos = g_rowptr[d] + atomicAdd(&g_cnt[d], 1);
    g_srcs[pos] = g_src[e];
}

// ---------------- layer 1 GEMM (K=4), fused alpha ----------------
__global__ __launch_bounds__(256) void k_gemm1(const float* __restrict__ x,
                                               const float* __restrict__ W,
                                               const float* __restrict__ asrc,
                                               const float* __restrict__ adst, int N) {
    __shared__ float Wsh[4 * 128];
    __shared__ float s_as[128], s_ad[128];
    int t = threadIdx.x;
    for (int i = t; i < 512; i += 256) Wsh[i] = W[i];
    if (t < 128) { s_as[t] = asrc[t]; s_ad[t] = adst[t]; }
    __syncthreads();
    int warp = t >> 5, lane = t & 31;
    int n = blockIdx.x * 8 + warp;
    if (n >= N) return;
    float4 xv = *(const float4*)(x + (size_t)n * 4);
    int j0 = lane * 4;
    float o[4];
    float ps = 0.f, pd = 0.f;
#pragma unroll
    for (int j = 0; j < 4; j++) {
        int c = j0 + j;
        float val = xv.x * Wsh[c] + xv.y * Wsh[128 + c] + xv.z * Wsh[256 + c] + xv.w * Wsh[384 + c];
        o[j] = val;
        ps = fmaf(val, s_as[c], ps);
        pd = fmaf(val, s_ad[c], pd);
    }
    *(float4*)(g_bufB + (size_t)n * FDIM + j0) = make_float4(o[0], o[1], o[2], o[3]);
#pragma unroll
    for (int off = 8; off >= 1; off >>= 1) {
        ps += __shfl_xor_sync(0xffffffffu, ps, off);
        pd += __shfl_xor_sync(0xffffffffu, pd, off);
    }
    if (lane == 0)  { g_asrc[n * 2]     = ps; g_adst[n * 2]     = pd; }
    if (lane == 16) { g_asrc[n * 2 + 1] = ps; g_adst[n * 2 + 1] = pd; }
}

// ---------------- mma.sync bf16 split-3 GEMM: 128x128 tile, K=128 ----------
// smem: A-hi/lo and B-hi/lo bf16 tiles [128][136] (pad 8 -> row stride 68
// words == 4 banks: conflict-free fragment loads), + alpha vectors.
#define MPAD 136
#define SM2_AHI 0
#define SM2_ALO (SM2_AHI + 128 * MPAD * 2)
#define SM2_BHI (SM2_ALO + 128 * MPAD * 2)
#define SM2_BLO (SM2_BHI + 128 * MPAD * 2)
#define SM2_AS  (SM2_BLO + 128 * MPAD * 2)
#define SM2_AD  (SM2_AS + 512)
#define SMEM_MMA_TOTAL (SM2_AD + 512)

__device__ __forceinline__ void split2bf(float v, uint16_t& hi, uint16_t& lo) {
    __nv_bfloat16 h = __float2bfloat16(v);
    float r = v - __bfloat162float(h);
    __nv_bfloat16 l = __float2bfloat16(r);
    hi = __bfloat16_as_ushort(h);
    lo = __bfloat16_as_ushort(l);
}

__device__ __forceinline__ void mma16816(float* c, const uint32_t* a, uint32_t b0, uint32_t b1) {
    asm volatile(
        "mma.sync.aligned.m16n8k16.row.col.f32.bf16.bf16.f32 "
        "{%0,%1,%2,%3}, {%4,%5,%6,%7}, {%8,%9}, {%0,%1,%2,%3};"
        : "+f"(c[0]), "+f"(c[1]), "+f"(c[2]), "+f"(c[3])
        : "r"(a[0]), "r"(a[1]), "r"(a[2]), "r"(a[3]), "r"(b0), "r"(b1));
}

__global__ __launch_bounds__(256, 1) void k_gemm_mma(const float* __restrict__ W,
                                                     const float* __restrict__ asrc,
                                                     const float* __restrict__ adst, int N) {
    extern __shared__ char smem[];
    __nv_bfloat16* Ahi = (__nv_bfloat16*)(smem + SM2_AHI);
    __nv_bfloat16* Alo = (__nv_bfloat16*)(smem + SM2_ALO);
    __nv_bfloat16* Bhi = (__nv_bfloat16*)(smem + SM2_BHI);
    __nv_bfloat16* Blo = (__nv_bfloat16*)(smem + SM2_BLO);
    float* s_as = (float*)(smem + SM2_AS);
    float* s_ad = (float*)(smem + SM2_AD);

    int t = threadIdx.x, wid = t >> 5, lane = t & 31;
    int rowBase = blockIdx.x * 128;
    if (t < 128) { s_as[t] = asrc[t]; s_ad[t] = adst[t]; }

    // --- A fill: g_bufA rows -> bf16 hi/lo, padded row-major ---
#pragma unroll
    for (int i = 0; i < 16; i++) {
        int idx = i * 256 + t;              // float4 index over 128x32
        int r = idx >> 5, c4 = idx & 31;
        int row = rowBase + r;
        float4 v = (row < N) ? *(const float4*)(g_bufA + (size_t)row * FDIM + c4 * 4)
                             : make_float4(0.f, 0.f, 0.f, 0.f);
        uint16_t h0, l0, h1, l1, h2, l2, h3, l3;
        split2bf(v.x, h0, l0); split2bf(v.y, h1, l1);
        split2bf(v.z, h2, l2); split2bf(v.w, h3, l3);
        int off = r * MPAD + c4 * 4;        // element offset (even -> 8B aligned)
        *(uint2*)(Ahi + off) = make_uint2((uint32_t)h0 | ((uint32_t)h1 << 16),
                                          (uint32_t)h2 | ((uint32_t)h3 << 16));
        *(uint2*)(Alo + off) = make_uint2((uint32_t)l0 | ((uint32_t)l1 << 16),
                                          (uint32_t)l2 | ((uint32_t)l3 << 16));
    }
    // --- B fill: B[n][k] = W[k][n]; coalesced gmem reads over n ---
#pragma unroll
    for (int i = 0; i < 32; i++) {
        int e = i * 256 + t;                // over 128 n x 64 k-pairs
        int n = e & 127, k = (e >> 7) * 2;
        float w0 = W[k * 128 + n];
        float w1 = W[(k + 1) * 128 + n];
        uint16_t h0, l0, h1, l1;
        split2bf(w0, h0, l0); split2bf(w1, h1, l1);
        int off = n * MPAD + k;
        *(uint32_t*)(Bhi + off) = (uint32_t)h0 | ((uint32_t)h1 << 16);
        *(uint32_t*)(Blo + off) = (uint32_t)l0 | ((uint32_t)l1 << 16);
    }
    __syncthreads();

    // warp grid 4x2: warp tile 32 rows x 64 cols (col half == head!)
    int wr = wid >> 1, wc = wid & 1;
    int g = lane >> 2, tq = lane & 3;
    int mrow = wr * 32, ncol = wc * 64;

    float acc[2][8][4];
#pragma unroll
    for (int i = 0; i < 2; i++)
#pragma unroll
        for (int j = 0; j < 8; j++)
#pragma unroll
            for (int q = 0; q < 4; q++) acc[i][j][q] = 0.f;

    const __nv_bfloat16* As[3] = { Ahi, Ahi, Alo };
    const __nv_bfloat16* Bs[3] = { Bhi, Blo, Bhi };
#pragma unroll
    for (int s = 0; s < 3; s++) {
        const __nv_bfloat16* A = As[s];
        const __nv_bfloat16* B = Bs[s];
#pragma unroll
        for (int kk = 0; kk < 8; kk++) {
            int k0 = kk * 16;
            uint32_t a[2][4];
#pragma unroll
            for (int i = 0; i < 2; i++) {
                int base = (mrow + i * 16 + g) * MPAD + k0 + 2 * tq;
                a[i][0] = *(const uint32_t*)(A + base);
                a[i][1] = *(const uint32_t*)(A + base + 8 * MPAD);
                a[i][2] = *(const uint32_t*)(A + base + 8);
                a[i][3] = *(const uint32_t*)(A + base + 8 * MPAD + 8);
            }
#pragma unroll
            for (int j = 0; j < 8; j++) {
                int bb = (ncol + j * 8 + g) * MPAD + k0 + 2 * tq;
                uint32_t b0 = *(const uint32_t*)(B + bb);
                uint32_t b1 = *(const uint32_t*)(B + bb + 8);
                mma16816(acc[0][j], a[0], b0, b1);
                mma16816(acc[1][j], a[1], b0, b1);
            }
        }
    }

    // --- epilogue: store D + fused alpha dots (head == wc) ---
#pragma unroll
    for (int i = 0; i < 2; i++) {
        int r0 = rowBase + mrow + i * 16 + g;
        int r1 = r0 + 8;
        float asA = 0.f, adA = 0.f, asB = 0.f, adB = 0.f;
#pragma unroll
        for (int j = 0; j < 8; j++) {
            int col = ncol + j * 8 + 2 * tq;
            float sa0 = s_as[col], sa1 = s_as[col + 1];
            float da0 = s_ad[col], da1 = s_ad[col + 1];
            asA = fmaf(acc[i][j][0], sa0, fmaf(acc[i][j][1], sa1, asA));
            adA = fmaf(acc[i][j][0], da0, fmaf(acc[i][j][1], da1, adA));
            asB = fmaf(acc[i][j][2], sa0, fmaf(acc[i][j][3], sa1, asB));
            adB = fmaf(acc[i][j][2], da0, fmaf(acc[i][j][3], da1, adB));
            if (r0 < N)
                *(float2*)(g_bufB + (size_t)r0 * FDIM + col) = make_float2(acc[i][j][0], acc[i][j][1]);
            if (r1 < N)
                *(float2*)(g_bufB + (size_t)r1 * FDIM + col) = make_float2(acc[i][j][2], acc[i][j][3]);
        }
        // reduce across the 4 lanes sharing a row (t bits 0-1)
#pragma unroll
        for (int off = 2; off >= 1; off >>= 1) {
            asA += __shfl_xor_sync(0xffffffffu, asA, off);
            adA += __shfl_xor_sync(0xffffffffu, adA, off);
            asB += __shfl_xor_sync(0xffffffffu, asB, off);
            adB += __shfl_xor_sync(0xffffffffu, adB, off);
        }
        if (tq == 0) {
            if (r0 < N) { g_asrc[r0 * 2 + wc] = asA; g_adst[r0 * 2 + wc] = adA; }
            if (r1 < N) { g_asrc[r1 * 2 + wc] = asB; g_adst[r1 * 2 + wc] = adB; }
        }
    }
}

// ---------------- aggregation: warp per dst node (CSR), no float atomics ----
__global__ __launch_bounds__(256) void k_agg(const float* __restrict__ bias, int N) {
    int warp = threadIdx.x >> 5, lane = threadIdx.x & 31;
    int v = blockIdx.x * 8 + warp;
    if (v >= N) return;
    int f0 = lane * 4;
    int head = lane >> 4;
    float4 bv = *(const float4*)(bias + f0);
    int start = g_rowptr[v], end = g_rowptr[v + 1];
    if (start == end) {
        float4 outv = make_float4(fmaxf(bv.x, 0.f), fmaxf(bv.y, 0.f),
                                  fmaxf(bv.z, 0.f), fmaxf(bv.w, 0.f));
        *(float4*)(g_bufA + (size_t)v * FDIM + f0) = outv;
        return;
    }
    float ad0 = g_adst[v * 2], ad1 = g_adst[v * 2 + 1];
    float m0 = -3e38f, m1 = -3e38f;
    for (int e = start + lane; e < end; e += 32) {
        int s = g_srcs[e];
        float2 as = *(const float2*)(g_asrc + s * 2);
        m0 = fmaxf(m0, lrelu(as.x + ad0));
        m1 = fmaxf(m1, lrelu(as.y + ad1));
    }
#pragma unroll
    for (int off = 16; off >= 1; off >>= 1) {
        m0 = fmaxf(m0, __shfl_xor_sync(0xffffffffu, m0, off));
        m1 = fmaxf(m1, __shfl_xor_sync(0xffffffffu, m1, off));
    }
    float d0 = 0.f, d1 = 0.f;
    float4 acc = make_float4(0.f, 0.f, 0.f, 0.f);
    for (int base = start; base < end; base += 32) {
        int e = base + lane;
        float w0 = 0.f, w1 = 0.f;
        int s = 0;
        if (e < end) {
            s = g_srcs[e];
            float2 as = *(const float2*)(g_asrc + s * 2);
            w0 = __expf(lrelu(as.x + ad0) - m0);
            w1 = __expf(lrelu(as.y + ad1) - m1);
            d0 += w0; d1 += w1;
        }
        int cnt = min(32, end - base);
        for (int i = 0; i < cnt; i++) {
            float ww0 = __shfl_sync(0xffffffffu, w0, i);
            float ww1 = __shfl_sync(0xffffffffu, w1, i);
            int   si  = __shfl_sync(0xffffffffu, s, i);
            float w   = head ? ww1 : ww0;
            float4 hv = *(const float4*)(g_bufB + (size_t)si * FDIM + f0);
            acc.x = fmaf(w, hv.x, acc.x);
            acc.y = fmaf(w, hv.y, acc.y);
            acc.z = fmaf(w, hv.z, acc.z);
            acc.w = fmaf(w, hv.w, acc.w);
        }
    }
#pragma unroll
    for (int off = 16; off >= 1; off >>= 1) {
        d0 += __shfl_xor_sync(0xffffffffu, d0, off);
        d1 += __shfl_xor_sync(0xffffffffu, d1, off);
    }
    float inv = 1.f / ((head ? d1 : d0) + 1e-16f);
    float4 outv;
    outv.x = fmaxf(fmaf(acc.x, inv, bv.x), 0.f);
    outv.y = fmaxf(fmaf(acc.y, inv, bv.y), 0.f);
    outv.z = fmaxf(fmaf(acc.z, inv, bv.z), 0.f);
    outv.w = fmaxf(fmaf(acc.w, inv, bv.w), 0.f);
    *(float4*)(g_bufA + (size_t)v * FDIM + f0) = outv;
}

// ---------------- pooling ----------------
__global__ void k_pool(int N) {
    int fg = blockIdx.y;
    int chunk = blockIdx.x * blockDim.x + threadIdx.x;
    int n0 = chunk * 16;
    if (n0 >= N) return;
    int f0 = fg * 4;
    int nend = min(n0 + 16, N);
    float4 acc = make_float4(0.f, 0.f, 0.f, 0.f);
    int cur = g_batch[n0];
    for (int n = n0; n < nend; n++) {
        int b = g_batch[n];
        if (b != cur) {
            atomicAdd(&g_gsum[cur * FDIM + f0 + 0], acc.x);
            atomicAdd(&g_gsum[cur * FDIM + f0 + 1], acc.y);
            atomicAdd(&g_gsum[cur * FDIM + f0 + 2], acc.z);
            atomicAdd(&g_gsum[cur * FDIM + f0 + 3], acc.w);
            acc = make_float4(0.f, 0.f, 0.f, 0.f);
            cur = b;
        }
        float4 v = *(const float4*)(g_bufA + (size_t)n * FDIM + f0);
        acc.x += v.x; acc.y += v.y; acc.z += v.z; acc.w += v.w;
    }
    atomicAdd(&g_gsum[cur * FDIM + f0 + 0], acc.x);
    atomicAdd(&g_gsum[cur * FDIM + f0 + 1], acc.y);
    atomicAdd(&g_gsum[cur * FDIM + f0 + 2], acc.z);
    atomicAdd(&g_gsum[cur * FDIM + f0 + 3], acc.w);
}

// ---------------- head ----------------
__global__ void k_head(const float* __restrict__ lw, const float* __restrict__ lb,
                       float* __restrict__ out) {
    int g = blockIdx.x, t = threadIdx.x;
    __shared__ float red[CDIM][128];
    float cnt = fmaxf((float)g_gcnt[g], 1.0f);
    float p = g_gsum[g * FDIM + t] / cnt;
#pragma unroll
    for (int c = 0; c < CDIM; c++) red[c][t] = p * lw[t * CDIM + c];
    __syncthreads();
    for (int s = 64; s >= 1; s >>= 1) {
        if (t < s) {
#pragma unroll
            for (int c = 0; c < CDIM; c++) red[c][t] += red[c][t + s];
        }
        __syncthreads();
    }
    if (t < CDIM) out[g * CDIM + t] = 1.f / (1.f + __expf(-(red[t][0] + lb[t])));
}

// ---------------- launch ----------------
extern "C" void kernel_launch(void* const* d_in, const int* in_sizes, int n_in,
                              void* d_out, int out_size) {
    const float* x   = (const float*)d_in[0];
    const void*  ei  = d_in[1];
    const void*  bt  = d_in[2];
    const float* W1  = (const float*)d_in[3];
    const float* as1 = (const float*)d_in[4];
    const float* ad1 = (const float*)d_in[5];
    const float* b1  = (const float*)d_in[6];
    const float* Wl[3]  = { (const float*)d_in[7],  (const float*)d_in[11], (const float*)d_in[15] };
    const float* asl[3] = { (const float*)d_in[8],  (const float*)d_in[12], (const float*)d_in[16] };
    const float* adl[3] = { (const float*)d_in[9],  (const float*)d_in[13], (const float*)d_in[17] };
    const float* bl[3]  = { (const float*)d_in[10], (const float*)d_in[14], (const float*)d_in[18] };
    const float* lw = (const float*)d_in[19];
    const float* lb = (const float*)d_in[20];

    int N = in_sizes[0] / 4;
    int E = in_sizes[1] / 2;
    int G = out_size / CDIM;

    cudaFuncSetAttribute(k_gemm_mma, cudaFuncAttributeMaxDynamicSharedMemorySize, SMEM_MMA_TOTAL);

    // preprocessing
    k_detect<<<1, 128>>>((const int*)ei, E);
    k_init<<<(N + 255) / 256, 256>>>(bt, N);
    k_convert_degree<<<(E + 255) / 256, 256>>>(ei, E);
    int nb = (N + SCB - 1) / SCB;
    k_scan1<<<nb, SCB>>>(N);
    k_scan2<<<1, 128>>>(nb);
    k_scan3<<<(N + 255) / 256, 256>>>(N, E);
    k_scatter<<<(E + 255) / 256, 256>>>(E);

    // layer 1
    k_gemm1<<<(N + 7) / 8, 256>>>(x, W1, as1, ad1, N);
    k_agg<<<(N + 7) / 8, 256>>>(b1, N);
    // layers 2..4 (tensor-core GEMM via mma.sync bf16 split-3)
    for (int l = 0; l < 3; l++) {
        k_gemm_mma<<<(N + 127) / 128, 256, SMEM_MMA_TOTAL>>>(Wl[l], asl[l], adl[l], N);
        k_agg<<<(N + 7) / 8, 256>>>(bl[l], N);
    }

    // pool + head
    int chunks = (N + 15) / 16;
    dim3 pg((chunks + 63) / 64, 32);
    k_pool<<<pg, 64>>>(N);
    k_head<<<G, 128>>>(lw, lb, (float*)d_out);
}

// round 14
// speedup vs baseline: 1.2313x; 1.0029x over previous
#include <cuda_runtime.h>
#include <cuda_bf16.h>
#include <math.h>
#include <stdint.h>

#define NMAX 50000
#define EMAX 500000
#define GMAX 64
#define FDIM 128
#define CDIM 5
#define NEG  0.2f

// ---------------- scratch (device globals; no allocation) ----------------
__device__ int   g_is64;
__device__ int   g_src[EMAX];
__device__ int   g_dst[EMAX];
__device__ int   g_batch[NMAX];
__device__ int   g_deg[NMAX];
__device__ int   g_cnt[NMAX];
__device__ int   g_rowptr[NMAX + 1];
__device__ int   g_srcs[EMAX];
__device__ int   g_bsum[128];
__device__ int   g_boff[128];
__device__ uint16_t g_bufAhi[(size_t)NMAX * FDIM];  // layer input, bf16 hi
__device__ uint16_t g_bufAlo[(size_t)NMAX * FDIM];  // layer input, bf16 lo
__device__ float g_bufB[(size_t)NMAX * FDIM];       // post-GEMM h (fp32, gathered by agg)
__device__ uint16_t g_Whi[FDIM * FDIM];             // W transposed [n][k], bf16 hi
__device__ uint16_t g_Wlo[FDIM * FDIM];             // W transposed [n][k], bf16 lo
__device__ float g_asrc[NMAX * 2];
__device__ float g_adst[NMAX * 2];
__device__ float g_gsum[GMAX * FDIM];
__device__ int   g_gcnt[GMAX];

__device__ __forceinline__ float lrelu(float x) { return x > 0.f ? x : NEG * x; }

__device__ __forceinline__ void split2bf(float v, uint16_t& hi, uint16_t& lo) {
    __nv_bfloat16 h = __float2bfloat16(v);
    float r = v - __bfloat162float(h);
    __nv_bfloat16 l = __float2bfloat16(r);
    hi = __bfloat16_as_ushort(h);
    lo = __bfloat16_as_ushort(l);
}
__device__ __forceinline__ float bfu(uint32_t u) {
    return __bfloat162float(__ushort_as_bfloat16((uint16_t)(u & 0xffffu)));
}

// ---------------- preprocessing ----------------
__global__ void k_detect(const int* __restrict__ ew, int E) {
    __shared__ int nz;
    if (threadIdx.x == 0) nz = 0;
    __syncthreads();
    int nsamp = E < 128 ? E : 128;
    if (threadIdx.x < nsamp && ew[2 * threadIdx.x + 1] != 0) atomicAdd(&nz, 1);
    for (int i = threadIdx.x; i < GMAX * FDIM; i += blockDim.x) g_gsum[i] = 0.f;
    for (int i = threadIdx.x; i < GMAX;        i += blockDim.x) g_gcnt[i] = 0;
    __syncthreads();
    if (threadIdx.x == 0) g_is64 = (nz == 0) ? 1 : 0;
}

__global__ void k_init(const void* __restrict__ bt, int N) {
    int n = blockIdx.x * blockDim.x + threadIdx.x;
    if (n >= N) return;
    g_deg[n] = 0;
    int b = g_is64 ? (int)((const long long*)bt)[n] : ((const int*)bt)[n];
    g_batch[n] = b;
    atomicAdd(&g_gcnt[b], 1);
}

// fused convert + degree (one pass over the edge list)
__global__ void k_convert_degree(const void* __restrict__ ei, int E) {
    int e = blockIdx.x * blockDim.x + threadIdx.x;
    if (e >= E) return;
    int s, d;
    if (g_is64) {
        const long long* p = (const long long*)ei;
        s = (int)p[e]; d = (int)p[(size_t)E + e];
    } else {
        const int* p = (const int*)ei;
        s = p[e]; d = p[E + e];
    }
    g_src[e] = s; g_dst[e] = d;
    atomicAdd(&g_deg[d], 1);
}

#define SCB 1024
__global__ void k_scan1(int N) {
    __shared__ int sh[SCB];
    int i = blockIdx.x * SCB + threadIdx.x;
    int v = (i < N) ? g_deg[i] : 0;
    sh[threadIdx.x] = v;
    __syncthreads();
    for (int off = 1; off < SCB; off <<= 1) {
        int t = (threadIdx.x >= off) ? sh[threadIdx.x - off] : 0;
        __syncthreads();
        sh[threadIdx.x] += t;
        __syncthreads();
    }
    if (i < N) g_rowptr[i] = sh[threadIdx.x] - v;
    if (threadIdx.x == SCB - 1) g_bsum[blockIdx.x] = sh[SCB - 1];
}

__global__ void k_scan2(int nb) {
    __shared__ int sh[128];
    int v = (threadIdx.x < nb) ? g_bsum[threadIdx.x] : 0;
    sh[threadIdx.x] = v;
    __syncthreads();
    for (int off = 1; off < 128; off <<= 1) {
        int t = (threadIdx.x >= off) ? sh[threadIdx.x - off] : 0;
        __syncthreads();
        sh[threadIdx.x] += t;
        __syncthreads();
    }
    g_boff[threadIdx.x] = sh[threadIdx.x] - v;
}

__global__ void k_scan3(int N, int E) {
    int i = blockIdx.x * blockDim.x + threadIdx.x;
    if (i < N) {
        g_rowptr[i] += g_boff[i / SCB];
        g_cnt[i] = 0;
    }
    if (i == 0) g_rowptr[N] = E;
}

__global__ void k_scatter(int E) {
    int e = blockIdx.x * blockDim.x + threadIdx.x;
    if (e >= E) return;
    int d = g_dst[e];
    int pos = g_rowptr[d] + atomicAdd(&g_cnt[d], 1);
    g_srcs[pos] = g_src[e];
}

// ---------------- W split + transpose (once per layer) ----------------
__global__ void k_wsplit(const float* __restrict__ W) {
    int idx = blockIdx.x * blockDim.x + threadIdx.x;    // 16384
    int k = idx >> 7, n = idx & 127;
    uint16_t h, l;
    split2bf(W[idx], h, l);                              // W[k][n]
    g_Whi[n * FDIM + k] = h;
    g_Wlo[n * FDIM + k] = l;
}

// ---------------- layer 1 GEMM (K=4), fused alpha ----------------
__global__ __launch_bounds__(256) void k_gemm1(const float* __restrict__ x,
                                               const float* __restrict__ W,
                                               const float* __restrict__ asrc,
                                               const float* __restrict__ adst, int N) {
    __shared__ float Wsh[4 * 128];
    __shared__ float s_as[128], s_ad[128];
    int t = threadIdx.x;
    for (int i = t; i < 512; i += 256) Wsh[i] = W[i];
    if (t < 128) { s_as[t] = asrc[t]; s_ad[t] = adst[t]; }
    __syncthreads();
    int warp = t >> 5, lane = t & 31;
    int n = blockIdx.x * 8 + warp;
    if (n >= N) return;
    float4 xv = *(const float4*)(x + (size_t)n * 4);
    int j0 = lane * 4;
    float o[4];
    float ps = 0.f, pd = 0.f;
#pragma unroll
    for (int j = 0; j < 4; j++) {
        int c = j0 + j;
        float val = xv.x * Wsh[c] + xv.y * Wsh[128 + c] + xv.z * Wsh[256 + c] + xv.w * Wsh[384 + c];
        o[j] = val;
        ps = fmaf(val, s_as[c], ps);
        pd = fmaf(val, s_ad[c], pd);
    }
    *(float4*)(g_bufB + (size_t)n * FDIM + j0) = make_float4(o[0], o[1], o[2], o[3]);
#pragma unroll
    for (int off = 8; off >= 1; off >>= 1) {
        ps += __shfl_xor_sync(0xffffffffu, ps, off);
        pd += __shfl_xor_sync(0xffffffffu, pd, off);
    }
    if (lane == 0)  { g_asrc[n * 2]     = ps; g_adst[n * 2]     = pd; }
    if (lane == 16) { g_asrc[n * 2 + 1] = ps; g_adst[n * 2 + 1] = pd; }
}

// ---------------- mma.sync bf16 split-3 GEMM: 128x128 tile, K=128 ----------
// Fill is now a pure copy (operands pre-split in gmem).
#define MPAD 136
#define SM2_AHI 0
#define SM2_ALO (SM2_AHI + 128 * MPAD * 2)
#define SM2_BHI (SM2_ALO + 128 * MPAD * 2)
#define SM2_BLO (SM2_BHI + 128 * MPAD * 2)
#define SM2_AS  (SM2_BLO + 128 * MPAD * 2)
#define SM2_AD  (SM2_AS + 512)
#define SMEM_MMA_TOTAL (SM2_AD + 512)

__device__ __forceinline__ void mma16816(float* c, const uint32_t* a, uint32_t b0, uint32_t b1) {
    asm volatile(
        "mma.sync.aligned.m16n8k16.row.col.f32.bf16.bf16.f32 "
        "{%0,%1,%2,%3}, {%4,%5,%6,%7}, {%8,%9}, {%0,%1,%2,%3};"
        : "+f"(c[0]), "+f"(c[1]), "+f"(c[2]), "+f"(c[3])
        : "r"(a[0]), "r"(a[1]), "r"(a[2]), "r"(a[3]), "r"(b0), "r"(b1));
}

__global__ __launch_bounds__(256, 1) void k_gemm_mma(const float* __restrict__ asrc,
                                                     const float* __restrict__ adst, int N) {
    extern __shared__ char smem[];
    __nv_bfloat16* Ahi = (__nv_bfloat16*)(smem + SM2_AHI);
    __nv_bfloat16* Alo = (__nv_bfloat16*)(smem + SM2_ALO);
    __nv_bfloat16* Bhi = (__nv_bfloat16*)(smem + SM2_BHI);
    __nv_bfloat16* Blo = (__nv_bfloat16*)(smem + SM2_BLO);
    float* s_as = (float*)(smem + SM2_AS);
    float* s_ad = (float*)(smem + SM2_AD);

    int t = threadIdx.x, wid = t >> 5, lane = t & 31;
    int rowBase = blockIdx.x * 128;
    if (t < 128) { s_as[t] = asrc[t]; s_ad[t] = adst[t]; }

    // --- A fill: pure uint2 copy from pre-split gmem ---
#pragma unroll
    for (int i = 0; i < 16; i++) {
        int idx = i * 256 + t;               // uint2 index over 128 rows x 32 chunks
        int r = idx >> 5, c4 = idx & 31;     // c4: 4-bf16 chunk
        int row = rowBase + r;
        uint2 hv = make_uint2(0u, 0u), lv = make_uint2(0u, 0u);
        if (row < N) {
            hv = *(const uint2*)(g_bufAhi + (size_t)row * FDIM + c4 * 4);
            lv = *(const uint2*)(g_bufAlo + (size_t)row * FDIM + c4 * 4);
        }
        int off = r * MPAD + c4 * 4;
        *(uint2*)(Ahi + off) = hv;
        *(uint2*)(Alo + off) = lv;
    }
    // --- B fill: pure uint2 copy of transposed pre-split W ---
#pragma unroll
    for (int i = 0; i < 16; i++) {
        int idx = i * 256 + t;
        int n = idx >> 5, c4 = idx & 31;
        uint2 hv = *(const uint2*)(g_Whi + n * FDIM + c4 * 4);
        uint2 lv = *(const uint2*)(g_Wlo + n * FDIM + c4 * 4);
        int off = n * MPAD + c4 * 4;
        *(uint2*)(Bhi + off) = hv;
        *(uint2*)(Blo + off) = lv;
    }
    __syncthreads();

    // warp grid 4x2: warp tile 32 rows x 64 cols (col half == head!)
    int wr = wid >> 1, wc = wid & 1;
    int g = lane >> 2, tq = lane & 3;
    int mrow = wr * 32, ncol = wc * 64;

    float acc[2][8][4];
#pragma unroll
    for (int i = 0; i < 2; i++)
#pragma unroll
        for (int j = 0; j < 8; j++)
#pragma unroll
            for (int q = 0; q < 4; q++) acc[i][j][q] = 0.f;

    const __nv_bfloat16* As[3] = { Ahi, Ahi, Alo };
    const __nv_bfloat16* Bs[3] = { Bhi, Blo, Bhi };
#pragma unroll
    for (int s = 0; s < 3; s++) {
        const __nv_bfloat16* A = As[s];
        const __nv_bfloat16* B = Bs[s];
#pragma unroll
        for (int kk = 0; kk < 8; kk++) {
            int k0 = kk * 16;
            uint32_t a[2][4];
#pragma unroll
            for (int i = 0; i < 2; i++) {
                int base = (mrow + i * 16 + g) * MPAD + k0 + 2 * tq;
                a[i][0] = *(const uint32_t*)(A + base);
                a[i][1] = *(const uint32_t*)(A + base + 8 * MPAD);
                a[i][2] = *(const uint32_t*)(A + base + 8);
                a[i][3] = *(const uint32_t*)(A + base + 8 * MPAD + 8);
            }
#pragma unroll
            for (int j = 0; j < 8; j++) {
                int bb = (ncol + j * 8 + g) * MPAD + k0 + 2 * tq;
                uint32_t b0 = *(const uint32_t*)(B + bb);
                uint32_t b1 = *(const uint32_t*)(B + bb + 8);
                mma16816(acc[0][j], a[0], b0, b1);
                mma16816(acc[1][j], a[1], b0, b1);
            }
        }
    }

    // --- epilogue: store D (fp32, for agg gather) + fused alpha dots ---
#pragma unroll
    for (int i = 0; i < 2; i++) {
        int r0 = rowBase + mrow + i * 16 + g;
        int r1 = r0 + 8;
        float asA = 0.f, adA = 0.f, asB = 0.f, adB = 0.f;
#pragma unroll
        for (int j = 0; j < 8; j++) {
            int col = ncol + j * 8 + 2 * tq;
            float sa0 = s_as[col], sa1 = s_as[col + 1];
            float da0 = s_ad[col], da1 = s_ad[col + 1];
            asA = fmaf(acc[i][j][0], sa0, fmaf(acc[i][j][1], sa1, asA));
            adA = fmaf(acc[i][j][0], da0, fmaf(acc[i][j][1], da1, adA));
            asB = fmaf(acc[i][j][2], sa0, fmaf(acc[i][j][3], sa1, asB));
            adB = fmaf(acc[i][j][2], da0, fmaf(acc[i][j][3], da1, adB));
            if (r0 < N)
                *(float2*)(g_bufB + (size_t)r0 * FDIM + col) = make_float2(acc[i][j][0], acc[i][j][1]);
            if (r1 < N)
                *(float2*)(g_bufB + (size_t)r1 * FDIM + col) = make_float2(acc[i][j][2], acc[i][j][3]);
        }
#pragma unroll
        for (int off = 2; off >= 1; off >>= 1) {
            asA += __shfl_xor_sync(0xffffffffu, asA, off);
            adA += __shfl_xor_sync(0xffffffffu, adA, off);
            asB += __shfl_xor_sync(0xffffffffu, asB, off);
            adB += __shfl_xor_sync(0xffffffffu, adB, off);
        }
        if (tq == 0) {
            if (r0 < N) { g_asrc[r0 * 2 + wc] = asA; g_adst[r0 * 2 + wc] = adA; }
            if (r1 < N) { g_asrc[r1 * 2 + wc] = asB; g_adst[r1 * 2 + wc] = adB; }
        }
    }
}

// ---------------- aggregation: warp per dst node (CSR), no float atomics ----
// Output written directly as bf16 hi/lo pairs (next GEMM's A operand).
__device__ __forceinline__ void store_hilo(size_t off, float4 v) {
    uint16_t h0, l0, h1, l1, h2, l2, h3, l3;
    split2bf(v.x, h0, l0); split2bf(v.y, h1, l1);
    split2bf(v.z, h2, l2); split2bf(v.w, h3, l3);
    *(uint2*)(g_bufAhi + off) = make_uint2((uint32_t)h0 | ((uint32_t)h1 << 16),
                                           (uint32_t)h2 | ((uint32_t)h3 << 16));
    *(uint2*)(g_bufAlo + off) = make_uint2((uint32_t)l0 | ((uint32_t)l1 << 16),
                                           (uint32_t)l2 | ((uint32_t)l3 << 16));
}

__global__ __launch_bounds__(256) void k_agg(const float* __restrict__ bias, int N) {
    int warp = threadIdx.x >> 5, lane = threadIdx.x & 31;
    int v = blockIdx.x * 8 + warp;
    if (v >= N) return;
    int f0 = lane * 4;
    int head = lane >> 4;
    float4 bv = *(const float4*)(bias + f0);
    int start = g_rowptr[v], end = g_rowptr[v + 1];
    if (start == end) {
        float4 outv = make_float4(fmaxf(bv.x, 0.f), fmaxf(bv.y, 0.f),
                                  fmaxf(bv.z, 0.f), fmaxf(bv.w, 0.f));
        store_hilo((size_t)v * FDIM + f0, outv);
        return;
    }
    float ad0 = g_adst[v * 2], ad1 = g_adst[v * 2 + 1];
    float m0 = -3e38f, m1 = -3e38f;
    for (int e = start + lane; e < end; e += 32) {
        int s = g_srcs[e];
        float2 as = *(const float2*)(g_asrc + s * 2);
        m0 = fmaxf(m0, lrelu(as.x + ad0));
        m1 = fmaxf(m1, lrelu(as.y + ad1));
    }
#pragma unroll
    for (int off = 16; off >= 1; off >>= 1) {
        m0 = fmaxf(m0, __shfl_xor_sync(0xffffffffu, m0, off));
        m1 = fmaxf(m1, __shfl_xor_sync(0xffffffffu, m1, off));
    }
    float d0 = 0.f, d1 = 0.f;
    float4 acc = make_float4(0.f, 0.f, 0.f, 0.f);
    for (int base = start; base < end; base += 32) {
        int e = base + lane;
        float w0 = 0.f, w1 = 0.f;
        int s = 0;
        if (e < end) {
            s = g_srcs[e];
            float2 as = *(const float2*)(g_asrc + s * 2);
            w0 = __expf(lrelu(as.x + ad0) - m0);
            w1 = __expf(lrelu(as.y + ad1) - m1);
            d0 += w0; d1 += w1;
        }
        int cnt = min(32, end - base);
        for (int i = 0; i < cnt; i++) {
            float ww0 = __shfl_sync(0xffffffffu, w0, i);
            float ww1 = __shfl_sync(0xffffffffu, w1, i);
            int   si  = __shfl_sync(0xffffffffu, s, i);
            float w   = head ? ww1 : ww0;
            float4 hv = *(const float4*)(g_bufB + (size_t)si * FDIM + f0);
            acc.x = fmaf(w, hv.x, acc.x);
            acc.y = fmaf(w, hv.y, acc.y);
            acc.z = fmaf(w, hv.z, acc.z);
            acc.w = fmaf(w, hv.w, acc.w);
        }
    }
#pragma unroll
    for (int off = 16; off >= 1; off >>= 1) {
        d0 += __shfl_xor_sync(0xffffffffu, d0, off);
        d1 += __shfl_xor_sync(0xffffffffu, d1, off);
    }
    float inv = 1.f / ((head ? d1 : d0) + 1e-16f);
    float4 outv;
    outv.x = fmaxf(fmaf(acc.x, inv, bv.x), 0.f);
    outv.y = fmaxf(fmaf(acc.y, inv, bv.y), 0.f);
    outv.z = fmaxf(fmaf(acc.z, inv, bv.z), 0.f);
    outv.w = fmaxf(fmaf(acc.w, inv, bv.w), 0.f);
    store_hilo((size_t)v * FDIM + f0, outv);
}

// ---------------- pooling (reads bf16 hi/lo pairs) ----------------
__global__ void k_pool(int N) {
    int fg = blockIdx.y;
    int chunk = blockIdx.x * blockDim.x + threadIdx.x;
    int n0 = chunk * 16;
    if (n0 >= N) return;
    int f0 = fg * 4;
    int nend = min(n0 + 16, N);
    float4 acc = make_float4(0.f, 0.f, 0.f, 0.f);
    int cur = g_batch[n0];
    for (int n = n0; n < nend; n++) {
        int b = g_batch[n];
        if (b != cur) {
            atomicAdd(&g_gsum[cur * FDIM + f0 + 0], acc.x);
            atomicAdd(&g_gsum[cur * FDIM + f0 + 1], acc.y);
            atomicAdd(&g_gsum[cur * FDIM + f0 + 2], acc.z);
            atomicAdd(&g_gsum[cur * FDIM + f0 + 3], acc.w);
            acc = make_float4(0.f, 0.f, 0.f, 0.f);
            cur = b;
        }
        size_t off = (size_t)n * FDIM + f0;
        uint2 hv = *(const uint2*)(g_bufAhi + off);
        uint2 lv = *(const uint2*)(g_bufAlo + off);
        acc.x += bfu(hv.x) + bfu(lv.x);
        acc.y += bfu(hv.x >> 16) + bfu(lv.x >> 16);
        acc.z += bfu(hv.y) + bfu(lv.y);
        acc.w += bfu(hv.y >> 16) + bfu(lv.y >> 16);
    }
    atomicAdd(&g_gsum[cur * FDIM + f0 + 0], acc.x);
    atomicAdd(&g_gsum[cur * FDIM + f0 + 1], acc.y);
    atomicAdd(&g_gsum[cur * FDIM + f0 + 2], acc.z);
    atomicAdd(&g_gsum[cur * FDIM + f0 + 3], acc.w);
}

// ---------------- head ----------------
__global__ void k_head(const float* __restrict__ lw, const float* __restrict__ lb,
                       float* __restrict__ out) {
    int g = blockIdx.x, t = threadIdx.x;
    __shared__ float red[CDIM][128];
    float cnt = fmaxf((float)g_gcnt[g], 1.0f);
    float p = g_gsum[g * FDIM + t] / cnt;
#pragma unroll
    for (int c = 0; c < CDIM; c++) red[c][t] = p * lw[t * CDIM + c];
    __syncthreads();
    for (int s = 64; s >= 1; s >>= 1) {
        if (t < s) {
#pragma unroll
            for (int c = 0; c < CDIM; c++) red[c][t] += red[c][t + s];
        }
        __syncthreads();
    }
    if (t < CDIM) out[g * CDIM + t] = 1.f / (1.f + __expf(-(red[t][0] + lb[t])));
}

// ---------------- launch ----------------
extern "C" void kernel_launch(void* const* d_in, const int* in_sizes, int n_in,
                              void* d_out, int out_size) {
    const float* x   = (const float*)d_in[0];
    const void*  ei  = d_in[1];
    const void*  bt  = d_in[2];
    const float* W1  = (const float*)d_in[3];
    const float* as1 = (const float*)d_in[4];
    const float* ad1 = (const float*)d_in[5];
    const float* b1  = (const float*)d_in[6];
    const float* Wl[3]  = { (const float*)d_in[7],  (const float*)d_in[11], (const float*)d_in[15] };
    const float* asl[3] = { (const float*)d_in[8],  (const float*)d_in[12], (const float*)d_in[16] };
    const float* adl[3] = { (const float*)d_in[9],  (const float*)d_in[13], (const float*)d_in[17] };
    const float* bl[3]  = { (const float*)d_in[10], (const float*)d_in[14], (const float*)d_in[18] };
    const float* lw = (const float*)d_in[19];
    const float* lb = (const float*)d_in[20];

    int N = in_sizes[0] / 4;
    int E = in_sizes[1] / 2;
    int G = out_size / CDIM;

    cudaFuncSetAttribute(k_gemm_mma, cudaFuncAttributeMaxDynamicSharedMemorySize, SMEM_MMA_TOTAL);

    // preprocessing
    k_detect<<<1, 128>>>((const int*)ei, E);
    k_init<<<(N + 255) / 256, 256>>>(bt, N);
    k_convert_degree<<<(E + 255) / 256, 256>>>(ei, E);
    int nb = (N + SCB - 1) / SCB;
    k_scan1<<<nb, SCB>>>(N);
    k_scan2<<<1, 128>>>(nb);
    k_scan3<<<(N + 255) / 256, 256>>>(N, E);
    k_scatter<<<(E + 255) / 256, 256>>>(E);

    // layer 1
    k_gemm1<<<(N + 7) / 8, 256>>>(x, W1, as1, ad1, N);
    k_agg<<<(N + 7) / 8, 256>>>(b1, N);
    // layers 2..4 (tensor-core GEMM; W pre-split+transposed per layer)
    for (int l = 0; l < 3; l++) {
        k_wsplit<<<64, 256>>>(Wl[l]);
        k_gemm_mma<<<(N + 127) / 128, 256, SMEM_MMA_TOTAL>>>(asl[l], adl[l], N);
        k_agg<<<(N + 7) / 8, 256>>>(bl[l], N);
    }

    // pool + head
    int chunks = (N + 15) / 16;
    dim3 pg((chunks + 63) / 64, 32);
    k_pool<<<pg, 64>>>(N);
    k_head<<<G, 128>>>(lw, lb, (float*)d_out);
}